// round 6
// baseline (speedup 1.0000x reference)
#include <cuda_runtime.h>
#include <cuda_fp16.h>
#include <cstdint>
#include <cfloat>

#define NFEAT  64
#define KH     512
#define TILE   256
#define WSTRX  136
#define WSTRW  72
#define XBYTES (TILE * WSTRX * 2)
#define WBYTES (KH * WSTRW * 2)
#define GRID   152
#define DELTA  0.02f

__device__ __align__(16) unsigned short g_Wimg[KH * WSTRW];   // fp16 W
__device__ __align__(16) float g_Wf[KH * NFEAT];              // fp32 W (exact pass)
__device__ int g_nflag;
__device__ int g_flags[500000];

#define SM_W  0
#define SM_X0 (WBYTES)
#define SM_T  (SM_X0 + 2 * XBYTES)
#define SM_H  (SM_T + KH * 4)
#define SM_TOTAL (SM_H + KH * 4)

__device__ __forceinline__ uint32_t smem_u32(const void* p){
    uint32_t a; asm("{ .reg .u64 t; cvta.to.shared.u64 t, %1; cvt.u32.u64 %0, t; }" : "=r"(a) : "l"(p));
    return a;
}

#define LDM4(r, addr) asm volatile( \
    "ldmatrix.sync.aligned.m8n8.x4.shared.b16 {%0,%1,%2,%3}, [%4];" \
    : "=r"((r)[0]), "=r"((r)[1]), "=r"((r)[2]), "=r"((r)[3]) : "r"(addr))

#define MMA(c, a, b0, b1) asm volatile( \
    "mma.sync.aligned.m16n8k16.row.col.f32.f16.f16.f32 " \
    "{%0,%1,%2,%3}, {%4,%5,%6,%7}, {%8,%9}, {%0,%1,%2,%3};" \
    : "+f"((c)[0]), "+f"((c)[1]), "+f"((c)[2]), "+f"((c)[3]) \
    : "r"((a)[0]), "r"((a)[1]), "r"((a)[2]), "r"((a)[3]), "r"(b0), "r"(b1))

__global__ void prep_k(const float* __restrict__ z){
    int idx = blockIdx.x * blockDim.x + threadIdx.x;
    if (idx >= KH * NFEAT) return;
    int r = idx / NFEAT, c = idx % NFEAT;
    float w = expf(z[idx]);
    g_Wimg[r * WSTRW + c] = __half_as_ushort(__float2half_rn(w));
    g_Wf[idx] = w;
}

__global__ void zero_k(float* __restrict__ A){
    int i = threadIdx.x;
    if (i < KH) A[i] = 0.0f;
    if (i == 0) g_nflag = 0;
}

__device__ __forceinline__ void split_pack(float a, float b, uint32_t& hi, uint32_t& lo){
    __half ha = __float2half_rn(a), hb = __float2half_rn(b);
    __half la = __float2half_rn(a - __half2float(ha));
    __half lb = __float2half_rn(b - __half2float(hb));
    hi = (uint32_t)__half_as_ushort(ha) | ((uint32_t)__half_as_ushort(hb) << 16);
    lo = (uint32_t)__half_as_ushort(la) | ((uint32_t)__half_as_ushort(lb) << 16);
}

// ── pass 1: fast fp16 GEMM + maxout/min with margin flagging ──
__global__ void __launch_bounds__(256, 1)
mnn_mma(const float* __restrict__ x, const float* __restrict__ t,
        float* __restrict__ y, float* __restrict__ A, int n, int ntiles)
{
    extern __shared__ char smem[];
    float* sT = (float*)(smem + SM_T);
    int*   sH = (int*)(smem + SM_H);

    const int tid  = threadIdx.x;
    const int wid  = tid >> 5;
    const int lane = tid & 31;
    const int q    = lane & 3;

    {
        const float4* src = (const float4*)g_Wimg;
        float4* dst = (float4*)(smem + SM_W);
        #pragma unroll 4
        for (int i = tid; i < WBYTES / 16; i += 256) dst[i] = src[i];
        for (int i = tid; i < KH; i += 256) { sT[i] = t[i]; sH[i] = 0; }
    }

    const uint32_t sWa = smem_u32(smem + SM_W);
    const uint32_t sXa = smem_u32(smem + SM_X0);

    const uint32_t bpre = (uint32_t)((lane & 7) + ((lane >> 4) << 3)) * (WSTRW * 2) + (((lane >> 3) & 1) << 4);
    const uint32_t apre0 = (uint32_t)(wid * 32 +      (lane & 15)) * (WSTRX * 2) + ((lane >> 4) << 4);
    const uint32_t apre1 = (uint32_t)(wid * 32 + 16 + (lane & 15)) * (WSTRX * 2) + ((lane >> 4) << 4);

    // stage first tile into buffer 0
    {
        unsigned short* sX = (unsigned short*)(smem + SM_X0);
        const int rbase = blockIdx.x * TILE;
        if (rbase < ntiles * TILE) {
            #pragma unroll 4
            for (int i = tid; i < TILE * 16; i += 256) {
                int row = i >> 4, c4 = i & 15;
                int gr = rbase + row; if (gr >= n) gr = n - 1;
                float4 v = ((const float4*)(x + (size_t)gr * NFEAT))[c4];
                uint32_t h01, l01, h23, l23;
                split_pack(v.x, v.y, h01, l01);
                split_pack(v.z, v.w, h23, l23);
                int b = row * WSTRX + c4 * 4;
                *(uint32_t*)(sX + b)      = h01;
                *(uint32_t*)(sX + b + 2)  = h23;
                *(uint32_t*)(sX + b + 64) = l01;
                *(uint32_t*)(sX + b + 66) = l23;
            }
        }
    }
    __syncthreads();

    int p = 0;
    for (int tile = blockIdx.x; tile < ntiles; tile += gridDim.x) {
        const int rbase = tile * TILE;
        const uint32_t sXb = sXa + (uint32_t)p * XBYTES;

        uint32_t ah[2][4][4], al[2][4][4];
        #pragma unroll
        for (int kc = 0; kc < 4; kc++) {
            LDM4(ah[0][kc], sXb + apre0 + kc * 32);
            LDM4(ah[1][kc], sXb + apre1 + kc * 32);
            LDM4(al[0][kc], sXb + apre0 + 128 + kc * 32);
            LDM4(al[1][kc], sXb + apre1 + 128 + kc * 32);
        }

        const int  ntile   = tile + gridDim.x;
        const bool hasNext = ntile < ntiles;
        const int  nrbase  = ntile * TILE;
        unsigned short* sXn = (unsigned short*)(smem + SM_X0 + (p ^ 1) * XBYTES);
        uint32_t hw[8][2], lw[8][2];

        auto ldg_chunk = [&](int k0){
            #pragma unroll
            for (int k = 0; k < 8; k++) {
                int i = tid + (k0 + k) * 256;
                int gr = nrbase + (i >> 4); if (gr >= n) gr = n - 1;
                float4 v = ((const float4*)(x + (size_t)gr * NFEAT))[i & 15];
                split_pack(v.x, v.y, hw[k][0], lw[k][0]);
                split_pack(v.z, v.w, hw[k][1], lw[k][1]);
            }
        };
        auto sts_chunk = [&](int k0){
            #pragma unroll
            for (int k = 0; k < 8; k++) {
                int i = tid + (k0 + k) * 256;
                int b = (i >> 4) * WSTRX + (i & 15) * 4;
                *(uint32_t*)(sXn + b)      = hw[k][0];
                *(uint32_t*)(sXn + b + 2)  = hw[k][1];
                *(uint32_t*)(sXn + b + 64) = lw[k][0];
                *(uint32_t*)(sXn + b + 66) = lw[k][1];
            }
        };

        float mn[4]  = {FLT_MAX, FLT_MAX, FLT_MAX, FLT_MAX};
        float mn2[4] = {FLT_MAX, FLT_MAX, FLT_MAX, FLT_MAX};
        float wm[4]  = {FLT_MAX, FLT_MAX, FLT_MAX, FLT_MAX};
        int   mi[4]  = {0, 0, 0, 0};

        auto do_group = [&](int g){
            float mx[4]  = {-FLT_MAX, -FLT_MAX, -FLT_MAX, -FLT_MAX};
            float mx2[4] = {-FLT_MAX, -FLT_MAX, -FLT_MAX, -FLT_MAX};
            int   ix[4]  = {0, 0, 0, 0};

            #pragma unroll 2
            for (int it = 0; it < 4; it++) {
                const int nb = g * 64 + it * 16;
                const uint32_t bb = sWa + (uint32_t)nb * (WSTRW * 2) + bpre;

                uint32_t bw[4][4];
                #pragma unroll
                for (int kc = 0; kc < 4; kc++) LDM4(bw[kc], bb + kc * 32);

                float aA[2][2][4] = {{{0,0,0,0},{0,0,0,0}},{{0,0,0,0},{0,0,0,0}}};
                float aB[2][2][4] = {{{0,0,0,0},{0,0,0,0}},{{0,0,0,0},{0,0,0,0}}};
                #pragma unroll
                for (int kc = 0; kc < 2; kc++)
                    #pragma unroll
                    for (int mt = 0; mt < 2; mt++)
                        #pragma unroll
                        for (int nh = 0; nh < 2; nh++) {
                            MMA(aA[mt][nh], ah[mt][kc],   bw[kc][2*nh],   bw[kc][2*nh+1]);
                            MMA(aB[mt][nh], ah[mt][kc+2], bw[kc+2][2*nh], bw[kc+2][2*nh+1]);
                        }
                #pragma unroll
                for (int kc = 0; kc < 2; kc++)
                    #pragma unroll
                    for (int mt = 0; mt < 2; mt++)
                        #pragma unroll
                        for (int nh = 0; nh < 2; nh++) {
                            MMA(aA[mt][nh], al[mt][kc],   bw[kc][2*nh],   bw[kc][2*nh+1]);
                            MMA(aB[mt][nh], al[mt][kc+2], bw[kc+2][2*nh], bw[kc+2][2*nh+1]);
                        }

                const int n0 = nb + 2 * q;
                float2 tv0 = *(const float2*)(sT + n0);
                float2 tv1 = *(const float2*)(sT + n0 + 8);
                #pragma unroll
                for (int mt = 0; mt < 2; mt++)
                    #pragma unroll
                    for (int rh = 0; rh < 2; rh++) {
                        const int sl = mt * 2 + rh;
                        float v[4];
                        int   vi[4] = {n0, n0 + 1, n0 + 8, n0 + 9};
                        v[0] = (aA[mt][0][rh*2]   + tv0.x) + aB[mt][0][rh*2];
                        v[1] = (aA[mt][0][rh*2+1] + tv0.y) + aB[mt][0][rh*2+1];
                        v[2] = (aA[mt][1][rh*2]   + tv1.x) + aB[mt][1][rh*2];
                        v[3] = (aA[mt][1][rh*2+1] + tv1.y) + aB[mt][1][rh*2+1];
                        #pragma unroll
                        for (int u = 0; u < 4; u++) {
                            if (v[u] > mx[sl]) { mx2[sl] = mx[sl]; mx[sl] = v[u]; ix[sl] = vi[u]; }
                            else if (v[u] > mx2[sl]) mx2[sl] = v[u];
                        }
                    }
            }

            #pragma unroll
            for (int sl = 0; sl < 4; sl++) {
                #pragma unroll
                for (int off = 1; off <= 2; off <<= 1) {
                    float ov  = __shfl_xor_sync(0xFFFFFFFFu, mx[sl], off);
                    float ov2 = __shfl_xor_sync(0xFFFFFFFFu, mx2[sl], off);
                    int   oi  = __shfl_xor_sync(0xFFFFFFFFu, ix[sl], off);
                    if (ov > mx[sl] || (ov == mx[sl] && oi < ix[sl])) {
                        mx2[sl] = fmaxf(mx[sl], ov2); mx[sl] = ov; ix[sl] = oi;
                    } else {
                        mx2[sl] = fmaxf(mx2[sl], ov);
                    }
                }
                if (mx[sl] < mn[sl]) {
                    mn2[sl] = mn[sl]; mn[sl] = mx[sl]; mi[sl] = ix[sl];
                    wm[sl] = mx[sl] - mx2[sl];
                } else {
                    mn2[sl] = fminf(mn2[sl], mx[sl]);
                }
            }
        };

        if (hasNext) ldg_chunk(0);
        #pragma unroll 1
        for (int g = 0; g < 4; g++) do_group(g);
        if (hasNext) { sts_chunk(0); ldg_chunk(8); }
        #pragma unroll 1
        for (int g = 4; g < 8; g++) do_group(g);
        if (hasNext) sts_chunk(8);

        if (q == 0) {
            #pragma unroll
            for (int sl = 0; sl < 4; sl++) {
                int row = rbase + wid * 32 + (lane >> 2) + sl * 8;
                if (row < n) {
                    bool flag = (mn2[sl] - mn[sl] < DELTA) || (wm[sl] < DELTA);
                    if (flag) {
                        int qi = atomicAdd(&g_nflag, 1);
                        g_flags[qi] = row;
                    } else {
                        y[row] = mn[sl];
                        atomicAdd(&sH[mi[sl]], 1);
                    }
                }
            }
        }
        __syncthreads();
        p ^= 1;
    }

    for (int i = tid; i < KH; i += 256) {
        int c = sH[i];
        if (c) atomicAdd(&A[i], (float)c);
    }
}

// ── pass 2: exact fp32 recompute for flagged rows (1 warp/row) ──
__global__ void __launch_bounds__(256, 1)
fix_k(const float* __restrict__ x, const float* __restrict__ t,
      float* __restrict__ y, float* __restrict__ A)
{
    const int lane  = threadIdx.x & 31;
    const int wglob = (blockIdx.x * 256 + threadIdx.x) >> 5;
    const int wstr  = (gridDim.x * 256) >> 5;
    const int total = g_nflag;
    const int nbase = (lane >> 2) * 64 + (lane & 3) * 16;

    for (int i = wglob; i < total; i += wstr) {
        const int row = g_flags[i];
        float xr[64];
        {
            const float4* xp = (const float4*)(x + (size_t)row * NFEAT);
            #pragma unroll
            for (int c = 0; c < 16; c++) {
                float4 v = xp[c];
                xr[4*c] = v.x; xr[4*c+1] = v.y; xr[4*c+2] = v.z; xr[4*c+3] = v.w;
            }
        }
        float best = -FLT_MAX; int bidx = nbase;
        #pragma unroll 1
        for (int nn = nbase; nn < nbase + 16; nn++) {
            const float4* wp = (const float4*)(g_Wf + nn * NFEAT);
            float a0 = 0, a1 = 0, a2 = 0, a3 = 0;
            #pragma unroll
            for (int c = 0; c < 16; c++) {
                float4 w4 = wp[c];
                a0 = fmaf(xr[4*c],   w4.x, a0);
                a1 = fmaf(xr[4*c+1], w4.y, a1);
                a2 = fmaf(xr[4*c+2], w4.z, a2);
                a3 = fmaf(xr[4*c+3], w4.w, a3);
            }
            float acc = ((a0 + a1) + (a2 + a3)) + t[nn];
            if (acc > best) { best = acc; bidx = nn; }   // ascending nn → first max
        }
        // argmax within group (4 lanes per group), tie → smaller idx
        #pragma unroll
        for (int off = 1; off <= 2; off <<= 1) {
            float ov = __shfl_xor_sync(0xFFFFFFFFu, best, off);
            int   oi = __shfl_xor_sync(0xFFFFFFFFu, bidx, off);
            if (ov > best || (ov == best && oi < bidx)) { best = ov; bidx = oi; }
        }
        // min across 8 groups, tie → smaller group (== smaller idx)
        #pragma unroll
        for (int off = 4; off <= 16; off <<= 1) {
            float ov = __shfl_xor_sync(0xFFFFFFFFu, best, off);
            int   oi = __shfl_xor_sync(0xFFFFFFFFu, bidx, off);
            if (ov < best || (ov == best && oi < bidx)) { best = ov; bidx = oi; }
        }
        if (lane == 0) {
            y[row] = best;
            atomicAdd(&A[bidx], 1.0f);
        }
    }
}

extern "C" void kernel_launch(void* const* d_in, const int* in_sizes, int n_in,
                              void* d_out, int out_size)
{
    const float* x = (const float*)d_in[0];   // [N, 64]
    const float* z = (const float*)d_in[1];   // [8, 64, 64]
    const float* t = (const float*)d_in[2];   // [8, 64]
    const int n = in_sizes[0] / NFEAT;
    const int ntiles = (n + TILE - 1) / TILE;

    float* y = (float*)d_out;
    float* A = (float*)d_out + n;

    cudaFuncSetAttribute(mnn_mma, cudaFuncAttributeMaxDynamicSharedMemorySize, SM_TOTAL);

    prep_k<<<(KH * NFEAT + 255) / 256, 256>>>(z);
    zero_k<<<1, KH>>>(A);

    int grid = ntiles < GRID ? ntiles : GRID;
    mnn_mma<<<grid, 256, SM_TOTAL>>>(x, t, y, A, n, ntiles);
    fix_k<<<GRID, 256>>>(x, t, y, A);
}

// round 7
// speedup vs baseline: 2.0905x; 2.0905x over previous
#include <cuda_runtime.h>
#include <cuda_fp16.h>
#include <cstdint>
#include <cfloat>

#define NFEAT  64
#define KH     512
#define TILE   256
#define WSTRX  136
#define WSTRW  72
#define XBYTES (TILE * WSTRX * 2)     // 69632
#define WBYTES (KH * WSTRW * 2)      // 73728
#define GRID   152
#define DELTA  0.015f

__device__ __align__(16) unsigned short g_Wh[KH * WSTRW];  // fp16 hi(w)
__device__ __align__(16) unsigned short g_Wl[KH * WSTRW];  // fp16 lo(w)
__device__ int g_nflag;
__device__ int g_flags[500032];

// ── pass-1 SMEM: WH | X0 | X1 | T | H | FLAGLIST | CNT ──
#define SM_W   0
#define SM_X0  (WBYTES)
#define SM_T   (SM_X0 + 2 * XBYTES)
#define SM_H   (SM_T + KH * 4)
#define SM_FL  (SM_H + KH * 4)
#define SM_CNT (SM_FL + TILE * 4)
#define SM_TOTAL1 (SM_CNT + 16)       // 218144

// ── pass-2 SMEM: WH | WL | X | T | H ──
#define SM2_WH 0
#define SM2_WL (WBYTES)
#define SM2_X  (2 * WBYTES)
#define SM2_T  (SM2_X + XBYTES)
#define SM2_H  (SM2_T + KH * 4)
#define SM_TOTAL2 (SM2_H + KH * 4)    // 221184

__device__ __forceinline__ uint32_t smem_u32(const void* p){
    uint32_t a; asm("{ .reg .u64 t; cvta.to.shared.u64 t, %1; cvt.u32.u64 %0, t; }" : "=r"(a) : "l"(p));
    return a;
}

#define LDM4(r, addr) asm volatile( \
    "ldmatrix.sync.aligned.m8n8.x4.shared.b16 {%0,%1,%2,%3}, [%4];" \
    : "=r"((r)[0]), "=r"((r)[1]), "=r"((r)[2]), "=r"((r)[3]) : "r"(addr))

#define MMA(c, a, b0, b1) asm volatile( \
    "mma.sync.aligned.m16n8k16.row.col.f32.f16.f16.f32 " \
    "{%0,%1,%2,%3}, {%4,%5,%6,%7}, {%8,%9}, {%0,%1,%2,%3};" \
    : "+f"((c)[0]), "+f"((c)[1]), "+f"((c)[2]), "+f"((c)[3]) \
    : "r"((a)[0]), "r"((a)[1]), "r"((a)[2]), "r"((a)[3]), "r"(b0), "r"(b1))

__global__ void prep_k(const float* __restrict__ z){
    int idx = blockIdx.x * blockDim.x + threadIdx.x;
    if (idx >= KH * NFEAT) return;
    int r = idx / NFEAT, c = idx % NFEAT;
    float w = expf(z[idx]);
    __half h = __float2half_rn(w);
    __half l = __float2half_rn(w - __half2float(h));
    g_Wh[r * WSTRW + c] = __half_as_ushort(h);
    g_Wl[r * WSTRW + c] = __half_as_ushort(l);
}

__global__ void zero_k(float* __restrict__ A){
    int i = threadIdx.x;
    if (i < KH) A[i] = 0.0f;
    if (i == 0) g_nflag = 0;
}

__device__ __forceinline__ void split_pack(float a, float b, uint32_t& hi, uint32_t& lo){
    __half ha = __float2half_rn(a), hb = __float2half_rn(b);
    __half la = __float2half_rn(a - __half2float(ha));
    __half lb = __float2half_rn(b - __half2float(hb));
    hi = (uint32_t)__half_as_ushort(ha) | ((uint32_t)__half_as_ushort(hb) << 16);
    lo = (uint32_t)__half_as_ushort(la) | ((uint32_t)__half_as_ushort(lb) << 16);
}

// branchless ordered top-2 insert (ascending index ⇒ strict > keeps first max)
#define UPD(sl, v, vidx) do { \
    float _lo = fminf((v), mx[sl]); \
    bool  _g  = (v) > mx[sl]; \
    mx2[sl] = fmaxf(mx2[sl], _lo); \
    mx[sl]  = _g ? (v) : mx[sl]; \
    ix[sl]  = _g ? (vidx) : ix[sl]; \
} while(0)

// ── pass 1: fp16 2-term GEMM + branchless margin flagging ──
__global__ void __launch_bounds__(256, 1)
mnn_fast(const float* __restrict__ x, const float* __restrict__ t,
         float* __restrict__ y, float* __restrict__ A, int n, int ntiles)
{
    extern __shared__ char smem[];
    float* sT  = (float*)(smem + SM_T);
    int*   sH  = (int*)(smem + SM_H);
    int*   sFL = (int*)(smem + SM_FL);
    int*   sC  = (int*)(smem + SM_CNT);

    const int tid  = threadIdx.x;
    const int wid  = tid >> 5;
    const int lane = tid & 31;
    const int q    = lane & 3;

    {
        const float4* src = (const float4*)g_Wh;
        float4* dst = (float4*)(smem + SM_W);
        #pragma unroll 4
        for (int i = tid; i < WBYTES / 16; i += 256) dst[i] = src[i];
        for (int i = tid; i < KH; i += 256) { sT[i] = t[i]; sH[i] = 0; }
        if (tid == 0) sC[0] = 0;
    }

    const uint32_t sWa = smem_u32(smem + SM_W);
    const uint32_t sXa = smem_u32(smem + SM_X0);

    const uint32_t bpre  = (uint32_t)((lane & 7) + ((lane >> 4) << 3)) * (WSTRW * 2) + (((lane >> 3) & 1) << 4);
    const uint32_t apre0 = (uint32_t)(wid * 32 +      (lane & 15)) * (WSTRX * 2) + ((lane >> 4) << 4);
    const uint32_t apre1 = (uint32_t)(wid * 32 + 16 + (lane & 15)) * (WSTRX * 2) + ((lane >> 4) << 4);

    // stage first tile into buffer 0
    {
        unsigned short* sX = (unsigned short*)(smem + SM_X0);
        const int rbase = blockIdx.x * TILE;
        if (rbase < ntiles * TILE) {
            #pragma unroll 4
            for (int i = tid; i < TILE * 16; i += 256) {
                int row = i >> 4, c4 = i & 15;
                int gr = rbase + row; if (gr >= n) gr = n - 1;
                float4 v = ((const float4*)(x + (size_t)gr * NFEAT))[c4];
                uint32_t h01, l01, h23, l23;
                split_pack(v.x, v.y, h01, l01);
                split_pack(v.z, v.w, h23, l23);
                int b = row * WSTRX + c4 * 4;
                *(uint32_t*)(sX + b)      = h01;
                *(uint32_t*)(sX + b + 2)  = h23;
                *(uint32_t*)(sX + b + 64) = l01;
                *(uint32_t*)(sX + b + 66) = l23;
            }
        }
    }
    __syncthreads();

    int p = 0;
    for (int tile = blockIdx.x; tile < ntiles; tile += gridDim.x) {
        const int rbase = tile * TILE;
        const uint32_t sXb = sXa + (uint32_t)p * XBYTES;

        uint32_t ah[2][4][4], al[2][4][4];
        #pragma unroll
        for (int kc = 0; kc < 4; kc++) {
            LDM4(ah[0][kc], sXb + apre0 + kc * 32);
            LDM4(ah[1][kc], sXb + apre1 + kc * 32);
            LDM4(al[0][kc], sXb + apre0 + 128 + kc * 32);
            LDM4(al[1][kc], sXb + apre1 + 128 + kc * 32);
        }

        const int  ntile   = tile + gridDim.x;
        const bool hasNext = ntile < ntiles;
        const int  nrbase  = ntile * TILE;
        unsigned short* sXn = (unsigned short*)(smem + SM_X0 + (p ^ 1) * XBYTES);
        uint32_t hw[8][2], lw[8][2];

        auto ldg_chunk = [&](int k0){
            #pragma unroll
            for (int k = 0; k < 8; k++) {
                int i = tid + (k0 + k) * 256;
                int gr = nrbase + (i >> 4); if (gr >= n) gr = n - 1;
                float4 v = ((const float4*)(x + (size_t)gr * NFEAT))[i & 15];
                split_pack(v.x, v.y, hw[k][0], lw[k][0]);
                split_pack(v.z, v.w, hw[k][1], lw[k][1]);
            }
        };
        auto sts_chunk = [&](int k0){
            #pragma unroll
            for (int k = 0; k < 8; k++) {
                int i = tid + (k0 + k) * 256;
                int b = (i >> 4) * WSTRX + (i & 15) * 4;
                *(uint32_t*)(sXn + b)      = hw[k][0];
                *(uint32_t*)(sXn + b + 2)  = hw[k][1];
                *(uint32_t*)(sXn + b + 64) = lw[k][0];
                *(uint32_t*)(sXn + b + 66) = lw[k][1];
            }
        };

        float mn[4]  = {FLT_MAX, FLT_MAX, FLT_MAX, FLT_MAX};
        float mn2[4] = {FLT_MAX, FLT_MAX, FLT_MAX, FLT_MAX};
        float wm[4]  = {FLT_MAX, FLT_MAX, FLT_MAX, FLT_MAX};
        int   mi[4]  = {0, 0, 0, 0};

        auto do_group = [&](int g){
            float mx[4]  = {-FLT_MAX, -FLT_MAX, -FLT_MAX, -FLT_MAX};
            float mx2[4] = {-FLT_MAX, -FLT_MAX, -FLT_MAX, -FLT_MAX};
            int   ix[4]  = {0, 0, 0, 0};

            #pragma unroll 2
            for (int it = 0; it < 4; it++) {
                const int nb = g * 64 + it * 16;
                const uint32_t bb = sWa + (uint32_t)nb * (WSTRW * 2) + bpre;

                uint32_t bw[4][4];
                #pragma unroll
                for (int kc = 0; kc < 4; kc++) LDM4(bw[kc], bb + kc * 32);

                float aA[2][2][4] = {{{0,0,0,0},{0,0,0,0}},{{0,0,0,0},{0,0,0,0}}};
                float aB[2][2][4] = {{{0,0,0,0},{0,0,0,0}},{{0,0,0,0},{0,0,0,0}}};
                #pragma unroll
                for (int kc = 0; kc < 2; kc++)
                    #pragma unroll
                    for (int mt = 0; mt < 2; mt++)
                        #pragma unroll
                        for (int nh = 0; nh < 2; nh++) {
                            MMA(aA[mt][nh], ah[mt][kc],   bw[kc][2*nh],   bw[kc][2*nh+1]);
                            MMA(aB[mt][nh], ah[mt][kc+2], bw[kc+2][2*nh], bw[kc+2][2*nh+1]);
                        }
                #pragma unroll
                for (int kc = 0; kc < 2; kc++)
                    #pragma unroll
                    for (int mt = 0; mt < 2; mt++)
                        #pragma unroll
                        for (int nh = 0; nh < 2; nh++) {
                            MMA(aA[mt][nh], al[mt][kc],   bw[kc][2*nh],   bw[kc][2*nh+1]);
                            MMA(aB[mt][nh], al[mt][kc+2], bw[kc+2][2*nh], bw[kc+2][2*nh+1]);
                        }

                const int n0 = nb + 2 * q;
                float2 tv0 = *(const float2*)(sT + n0);
                float2 tv1 = *(const float2*)(sT + n0 + 8);
                #pragma unroll
                for (int mt = 0; mt < 2; mt++)
                    #pragma unroll
                    for (int rh = 0; rh < 2; rh++) {
                        const int sl = mt * 2 + rh;
                        float v0 = (aA[mt][0][rh*2]   + tv0.x) + aB[mt][0][rh*2];
                        float v1 = (aA[mt][0][rh*2+1] + tv0.y) + aB[mt][0][rh*2+1];
                        float v2 = (aA[mt][1][rh*2]   + tv1.x) + aB[mt][1][rh*2];
                        float v3 = (aA[mt][1][rh*2+1] + tv1.y) + aB[mt][1][rh*2+1];
                        UPD(sl, v0, n0);
                        UPD(sl, v1, n0 + 1);
                        UPD(sl, v2, n0 + 8);
                        UPD(sl, v3, n0 + 9);
                    }
            }

            #pragma unroll
            for (int sl = 0; sl < 4; sl++) {
                #pragma unroll
                for (int off = 1; off <= 2; off <<= 1) {
                    float ov  = __shfl_xor_sync(0xFFFFFFFFu, mx[sl], off);
                    float ov2 = __shfl_xor_sync(0xFFFFFFFFu, mx2[sl], off);
                    int   oi  = __shfl_xor_sync(0xFFFFFFFFu, ix[sl], off);
                    bool take = (ov > mx[sl]) || (ov == mx[sl] && oi < ix[sl]);
                    float lo  = fminf(mx[sl], ov);
                    float s2  = take ? ov2 : mx2[sl];
                    mx[sl]  = take ? ov : mx[sl];
                    ix[sl]  = take ? oi : ix[sl];
                    mx2[sl] = fmaxf(lo, s2);
                }
                bool lt = mx[sl] < mn[sl];
                mn2[sl] = fminf(mn2[sl], lt ? mn[sl] : mx[sl]);
                wm[sl]  = lt ? (mx[sl] - mx2[sl]) : wm[sl];
                mi[sl]  = lt ? ix[sl] : mi[sl];
                mn[sl]  = lt ? mx[sl] : mn[sl];
            }
        };

        if (hasNext) ldg_chunk(0);
        #pragma unroll 1
        for (int g = 0; g < 4; g++) do_group(g);
        if (hasNext) { sts_chunk(0); ldg_chunk(8); }
        #pragma unroll 1
        for (int g = 4; g < 8; g++) do_group(g);
        if (hasNext) sts_chunk(8);

        if (q == 0) {
            #pragma unroll
            for (int sl = 0; sl < 4; sl++) {
                int row = rbase + wid * 32 + (lane >> 2) + sl * 8;
                if (row < n) {
                    bool flag = (mn2[sl] - mn[sl] < DELTA) || (wm[sl] < DELTA);
                    if (flag) {
                        int pos = atomicAdd(&sC[0], 1);
                        sFL[pos] = row;
                    } else {
                        y[row] = mn[sl];
                        atomicAdd(&sH[mi[sl]], 1);
                    }
                }
            }
        }
        __syncthreads();
        if (tid == 0 && sC[0] > 0) sC[1] = atomicAdd(&g_nflag, sC[0]);
        __syncthreads();
        {
            int cnt = sC[0], base = sC[1];
            __syncthreads();               // everyone has cnt/base before reset
            if (tid == 0) sC[0] = 0;
            for (int i = tid; i < cnt; i += 256) g_flags[base + i] = sFL[i];
        }
        __syncthreads();
        p ^= 1;
    }

    for (int i = tid; i < KH; i += 256) {
        int c = sH[i];
        if (c) atomicAdd(&A[i], (float)c);
    }
}

// ── pass 2: 3-term fp16 MMA recompute on gathered flagged rows ──
__global__ void __launch_bounds__(256, 1)
mnn_fix(const float* __restrict__ x, const float* __restrict__ t,
        float* __restrict__ y, float* __restrict__ A)
{
    extern __shared__ char smem[];
    unsigned short* sX = (unsigned short*)(smem + SM2_X);
    float* sT = (float*)(smem + SM2_T);
    int*   sH = (int*)(smem + SM2_H);

    const int tid  = threadIdx.x;
    const int wid  = tid >> 5;
    const int lane = tid & 31;
    const int q    = lane & 3;

    const int F = *(volatile int*)&g_nflag;
    const int vtiles = (F + TILE - 1) / TILE;

    {
        const float4* s1 = (const float4*)g_Wh;
        const float4* s2 = (const float4*)g_Wl;
        float4* d1 = (float4*)(smem + SM2_WH);
        float4* d2 = (float4*)(smem + SM2_WL);
        #pragma unroll 4
        for (int i = tid; i < WBYTES / 16; i += 256) { d1[i] = s1[i]; d2[i] = s2[i]; }
        for (int i = tid; i < KH; i += 256) { sT[i] = t[i]; sH[i] = 0; }
    }
    __syncthreads();

    const uint32_t sWHa = smem_u32(smem + SM2_WH);
    const uint32_t sWLa = smem_u32(smem + SM2_WL);
    const uint32_t sXa  = smem_u32(sX);

    const uint32_t bpre  = (uint32_t)((lane & 7) + ((lane >> 4) << 3)) * (WSTRW * 2) + (((lane >> 3) & 1) << 4);
    const uint32_t apre0 = (uint32_t)(wid * 32 +      (lane & 15)) * (WSTRX * 2) + ((lane >> 4) << 4);
    const uint32_t apre1 = (uint32_t)(wid * 32 + 16 + (lane & 15)) * (WSTRX * 2) + ((lane >> 4) << 4);

    for (int vt = blockIdx.x; vt < vtiles; vt += gridDim.x) {
        // gather-stage x rows for this virtual tile
        #pragma unroll 4
        for (int i = tid; i < TILE * 16; i += 256) {
            int rl = i >> 4, c4 = i & 15;
            int fi = vt * TILE + rl; if (fi >= F) fi = F - 1;
            int gr = g_flags[fi];
            float4 v = ((const float4*)(x + (size_t)gr * NFEAT))[c4];
            uint32_t h01, l01, h23, l23;
            split_pack(v.x, v.y, h01, l01);
            split_pack(v.z, v.w, h23, l23);
            int b = rl * WSTRX + c4 * 4;
            *(uint32_t*)(sX + b)      = h01;
            *(uint32_t*)(sX + b + 2)  = h23;
            *(uint32_t*)(sX + b + 64) = l01;
            *(uint32_t*)(sX + b + 66) = l23;
        }
        __syncthreads();

        uint32_t ah[2][4][4], al[2][4][4];
        #pragma unroll
        for (int kc = 0; kc < 4; kc++) {
            LDM4(ah[0][kc], sXa + apre0 + kc * 32);
            LDM4(ah[1][kc], sXa + apre1 + kc * 32);
            LDM4(al[0][kc], sXa + apre0 + 128 + kc * 32);
            LDM4(al[1][kc], sXa + apre1 + 128 + kc * 32);
        }

        float mn[4] = {FLT_MAX, FLT_MAX, FLT_MAX, FLT_MAX};
        int   mi[4] = {0, 0, 0, 0};

        #pragma unroll 1
        for (int g = 0; g < 8; g++) {
            float mx[4] = {-FLT_MAX, -FLT_MAX, -FLT_MAX, -FLT_MAX};
            int   ix[4] = {0, 0, 0, 0};

            #pragma unroll 2
            for (int it = 0; it < 4; it++) {
                const int nb = g * 64 + it * 16;
                const uint32_t bo = (uint32_t)nb * (WSTRW * 2) + bpre;

                uint32_t bh[4][4], bl2[4][4];
                #pragma unroll
                for (int kc = 0; kc < 4; kc++) {
                    LDM4(bh[kc],  sWHa + bo + kc * 32);
                    LDM4(bl2[kc], sWLa + bo + kc * 32);
                }

                float aA[2][2][4] = {{{0,0,0,0},{0,0,0,0}},{{0,0,0,0},{0,0,0,0}}};
                float aB[2][2][4] = {{{0,0,0,0},{0,0,0,0}},{{0,0,0,0},{0,0,0,0}}};
                #pragma unroll
                for (int kc = 0; kc < 2; kc++)
                    #pragma unroll
                    for (int mt = 0; mt < 2; mt++)
                        #pragma unroll
                        for (int nh = 0; nh < 2; nh++) {
                            MMA(aA[mt][nh], ah[mt][kc],   bh[kc][2*nh],   bh[kc][2*nh+1]);
                            MMA(aB[mt][nh], ah[mt][kc+2], bh[kc+2][2*nh], bh[kc+2][2*nh+1]);
                        }
                #pragma unroll
                for (int kc = 0; kc < 2; kc++)
                    #pragma unroll
                    for (int mt = 0; mt < 2; mt++)
                        #pragma unroll
                        for (int nh = 0; nh < 2; nh++) {
                            MMA(aA[mt][nh], al[mt][kc],   bh[kc][2*nh],   bh[kc][2*nh+1]);
                            MMA(aB[mt][nh], al[mt][kc+2], bh[kc+2][2*nh], bh[kc+2][2*nh+1]);
                        }
                #pragma unroll
                for (int kc = 0; kc < 2; kc++)
                    #pragma unroll
                    for (int mt = 0; mt < 2; mt++)
                        #pragma unroll
                        for (int nh = 0; nh < 2; nh++) {
                            MMA(aA[mt][nh], ah[mt][kc],   bl2[kc][2*nh],   bl2[kc][2*nh+1]);
                            MMA(aB[mt][nh], ah[mt][kc+2], bl2[kc+2][2*nh], bl2[kc+2][2*nh+1]);
                        }

                const int n0 = nb + 2 * q;
                float2 tv0 = *(const float2*)(sT + n0);
                float2 tv1 = *(const float2*)(sT + n0 + 8);
                #pragma unroll
                for (int mt = 0; mt < 2; mt++)
                    #pragma unroll
                    for (int rh = 0; rh < 2; rh++) {
                        const int sl = mt * 2 + rh;
                        float v0 = (aA[mt][0][rh*2]   + tv0.x) + aB[mt][0][rh*2];
                        float v1 = (aA[mt][0][rh*2+1] + tv0.y) + aB[mt][0][rh*2+1];
                        float v2 = (aA[mt][1][rh*2]   + tv1.x) + aB[mt][1][rh*2];
                        float v3 = (aA[mt][1][rh*2+1] + tv1.y) + aB[mt][1][rh*2+1];
                        if (v0 > mx[sl]) { mx[sl] = v0; ix[sl] = n0; }
                        if (v1 > mx[sl]) { mx[sl] = v1; ix[sl] = n0 + 1; }
                        if (v2 > mx[sl]) { mx[sl] = v2; ix[sl] = n0 + 8; }
                        if (v3 > mx[sl]) { mx[sl] = v3; ix[sl] = n0 + 9; }
                    }
            }

            #pragma unroll
            for (int sl = 0; sl < 4; sl++) {
                #pragma unroll
                for (int off = 1; off <= 2; off <<= 1) {
                    float ov = __shfl_xor_sync(0xFFFFFFFFu, mx[sl], off);
                    int   oi = __shfl_xor_sync(0xFFFFFFFFu, ix[sl], off);
                    if (ov > mx[sl] || (ov == mx[sl] && oi < ix[sl])) { mx[sl] = ov; ix[sl] = oi; }
                }
                if (mx[sl] < mn[sl]) { mn[sl] = mx[sl]; mi[sl] = ix[sl]; }
            }
        }

        if (q == 0) {
            #pragma unroll
            for (int sl = 0; sl < 4; sl++) {
                int fi = vt * TILE + wid * 32 + (lane >> 2) + sl * 8;
                if (fi < F) {
                    int row = g_flags[fi];
                    y[row] = mn[sl];
                    atomicAdd(&sH[mi[sl]], 1);
                }
            }
        }
        __syncthreads();   // hist + compute done before next gather restages sX
    }

    for (int i = tid; i < KH; i += 256) {
        int c = sH[i];
        if (c) atomicAdd(&A[i], (float)c);
    }
}

extern "C" void kernel_launch(void* const* d_in, const int* in_sizes, int n_in,
                              void* d_out, int out_size)
{
    const float* x = (const float*)d_in[0];   // [N, 64]
    const float* z = (const float*)d_in[1];   // [8, 64, 64]
    const float* t = (const float*)d_in[2];   // [8, 64]
    const int n = in_sizes[0] / NFEAT;
    const int ntiles = (n + TILE - 1) / TILE;

    float* y = (float*)d_out;
    float* A = (float*)d_out + n;

    cudaFuncSetAttribute(mnn_fast, cudaFuncAttributeMaxDynamicSharedMemorySize, SM_TOTAL1);
    cudaFuncSetAttribute(mnn_fix,  cudaFuncAttributeMaxDynamicSharedMemorySize, SM_TOTAL2);

    prep_k<<<(KH * NFEAT + 255) / 256, 256>>>(z);
    zero_k<<<1, KH>>>(A);

    int grid = ntiles < GRID ? ntiles : GRID;
    mnn_fast<<<grid, 256, SM_TOTAL1>>>(x, t, y, A, n, ntiles);
    mnn_fix<<<GRID, 256, SM_TOTAL2>>>(x, t, y, A);
}

// round 8
// speedup vs baseline: 2.3260x; 1.1126x over previous
#include <cuda_runtime.h>
#include <cuda_fp16.h>
#include <cstdint>
#include <cfloat>

#define NFEAT   64
#define KH      512
#define THREADS 384
#define NWARP   12
#define TILE    192            // NWARP * 16 rows
#define WSTRX   136            // X row stride (halves) = 272B, conflict-free ldmatrix
#define WSTRW   72             // W row stride (halves) = 144B
#define XBYTES  (TILE * WSTRX * 2)    // 52224
#define WBYTES  (KH * WSTRW * 2)      // 73728
#define GRID    152

__device__ __align__(16) unsigned short g_Wh[KH * WSTRW];
__device__ __align__(16) unsigned short g_Wl[KH * WSTRW];
__device__ int g_dummy;

// SMEM: Wh | Wl | X | T | H
#define SM_WH 0
#define SM_WL (WBYTES)
#define SM_X  (2 * WBYTES)            // 147456
#define SM_T  (SM_X + XBYTES)         // 199680
#define SM_H  (SM_T + KH * 4)         // 201728
#define SM_TOTAL (SM_H + KH * 4)      // 203776

__device__ __forceinline__ uint32_t smem_u32(const void* p){
    uint32_t a; asm("{ .reg .u64 t; cvta.to.shared.u64 t, %1; cvt.u32.u64 %0, t; }" : "=r"(a) : "l"(p));
    return a;
}

#define LDM4(r, addr) asm volatile( \
    "ldmatrix.sync.aligned.m8n8.x4.shared.b16 {%0,%1,%2,%3}, [%4];" \
    : "=r"((r)[0]), "=r"((r)[1]), "=r"((r)[2]), "=r"((r)[3]) : "r"(addr))

#define MMA(c, a, b0, b1) asm volatile( \
    "mma.sync.aligned.m16n8k16.row.col.f32.f16.f16.f32 " \
    "{%0,%1,%2,%3}, {%4,%5,%6,%7}, {%8,%9}, {%0,%1,%2,%3};" \
    : "+f"((c)[0]), "+f"((c)[1]), "+f"((c)[2]), "+f"((c)[3]) \
    : "r"((a)[0]), "r"((a)[1]), "r"((a)[2]), "r"((a)[3]), "r"(b0), "r"(b1))

__global__ void prep_k(const float* __restrict__ z){
    int idx = blockIdx.x * blockDim.x + threadIdx.x;
    if (idx >= KH * NFEAT) return;
    int r = idx / NFEAT, c = idx % NFEAT;
    float w = expf(z[idx]);
    __half h = __float2half_rn(w);
    __half l = __float2half_rn(w - __half2float(h));
    g_Wh[r * WSTRW + c] = __half_as_ushort(h);
    g_Wl[r * WSTRW + c] = __half_as_ushort(l);
}

__global__ void zero_k(float* __restrict__ A){
    int i = threadIdx.x;
    if (i < KH) A[i] = 0.0f;
}

__global__ void dummy_k(){
    if (threadIdx.x == 0) g_dummy = 1;
}

__device__ __forceinline__ void split_pack(float a, float b, uint32_t& hi, uint32_t& lo){
    __half ha = __float2half_rn(a), hb = __float2half_rn(b);
    __half la = __float2half_rn(a - __half2float(ha));
    __half lb = __float2half_rn(b - __half2float(hb));
    hi = (uint32_t)__half_as_ushort(ha) | ((uint32_t)__half_as_ushort(hb) << 16);
    lo = (uint32_t)__half_as_ushort(la) | ((uint32_t)__half_as_ushort(lb) << 16);
}

// ── main: persistent fp16 3-term GEMM + fused maxout/min/histogram ──
__global__ void __launch_bounds__(THREADS, 1)
mnn_mma(const float* __restrict__ x, const float* __restrict__ t,
        float* __restrict__ y, float* __restrict__ A, int n, int ntiles)
{
    extern __shared__ char smem[];
    unsigned short* sX = (unsigned short*)(smem + SM_X);
    float*          sT = (float*)(smem + SM_T);
    int*            sH = (int*)(smem + SM_H);

    const int tid  = threadIdx.x;
    const int wid  = tid >> 5;
    const int lane = tid & 31;
    const int q    = lane & 3;

    // Stage both W images + t + hist
    {
        const float4* s1 = (const float4*)g_Wh;
        const float4* s2 = (const float4*)g_Wl;
        float4* d1 = (float4*)(smem + SM_WH);
        float4* d2 = (float4*)(smem + SM_WL);
        #pragma unroll 4
        for (int i = tid; i < WBYTES / 16; i += THREADS) { d1[i] = s1[i]; d2[i] = s2[i]; }
        for (int i = tid; i < KH; i += THREADS) { sT[i] = t[i]; sH[i] = 0; }
    }

    const uint32_t sWHa = smem_u32(smem + SM_WH);
    const uint32_t sWLa = smem_u32(smem + SM_WL);
    const uint32_t sXa  = smem_u32(sX);

    // B ldmatrix x4 lane offset (n16 x k16 = 4 8x8 tiles)
    const uint32_t bpre = (uint32_t)((lane & 7) + ((lane >> 4) << 3)) * (WSTRW * 2) + (((lane >> 3) & 1) << 4);
    // A ldmatrix lane offset: m16 rows owned by this warp
    const uint32_t apre = (uint32_t)(wid * 16 + (lane & 15)) * (WSTRX * 2) + ((lane >> 4) << 4);

    // ── prologue: stage tile0 to SMEM, prefetch tile1 to regs ──
    {
        const int rbase0 = blockIdx.x * TILE;
        #pragma unroll
        for (int k = 0; k < 8; k++) {
            int i = tid + k * THREADS;
            int gr = rbase0 + (i >> 4); if (gr >= n) gr = n - 1;
            float4 v = ((const float4*)(x + (size_t)gr * NFEAT))[i & 15];
            uint32_t h01, l01, h23, l23;
            split_pack(v.x, v.y, h01, l01);
            split_pack(v.z, v.w, h23, l23);
            int b = (i >> 4) * WSTRX + (i & 15) * 4;
            *(uint32_t*)(sX + b)      = h01;
            *(uint32_t*)(sX + b + 2)  = h23;
            *(uint32_t*)(sX + b + 64) = l01;
            *(uint32_t*)(sX + b + 66) = l23;
        }
    }
    uint32_t hw[8][2], lw[8][2];      // prefetch regs (next tile)
    {
        const int t1 = blockIdx.x + GRID;
        if (t1 < ntiles) {
            const int rb = t1 * TILE;
            #pragma unroll
            for (int k = 0; k < 8; k++) {
                int i = tid + k * THREADS;
                int gr = rb + (i >> 4); if (gr >= n) gr = n - 1;
                float4 v = ((const float4*)(x + (size_t)gr * NFEAT))[i & 15];
                split_pack(v.x, v.y, hw[k][0], lw[k][0]);
                split_pack(v.z, v.w, hw[k][1], lw[k][1]);
            }
        }
    }
    __syncthreads();

    for (int tile = blockIdx.x; tile < ntiles; tile += GRID) {
        const int rbase = tile * TILE;
        const bool hasNext  = tile + GRID < ntiles;
        const bool hasNext2 = tile + 2 * GRID < ntiles;

        // A fragments (m16, K64, hi+lo)
        uint32_t ah[4][4], al[4][4];
        #pragma unroll
        for (int kc = 0; kc < 4; kc++) {
            LDM4(ah[kc], sXa + apre + kc * 32);
            LDM4(al[kc], sXa + apre + 128 + kc * 32);
        }
        __syncthreads();          // all A reads complete before overwrite

        // store prefetched tile i+1 into sX
        if (hasNext) {
            #pragma unroll
            for (int k = 0; k < 8; k++) {
                int i = tid + k * THREADS;
                int b = (i >> 4) * WSTRX + (i & 15) * 4;
                *(uint32_t*)(sX + b)      = hw[k][0];
                *(uint32_t*)(sX + b + 2)  = hw[k][1];
                *(uint32_t*)(sX + b + 64) = lw[k][0];
                *(uint32_t*)(sX + b + 66) = lw[k][1];
            }
        }

        float mn[2] = {FLT_MAX, FLT_MAX};
        int   mi[2] = {0, 0};

        auto do_group = [&](int g){
            float mx[2] = {-FLT_MAX, -FLT_MAX};
            int   ix[2] = {0, 0};

            #pragma unroll 2
            for (int it = 0; it < 4; it++) {
                const int nb = g * 64 + it * 16;
                const uint32_t bo = (uint32_t)nb * (WSTRW * 2) + bpre;

                uint32_t bh[4][4], bl[4][4];
                #pragma unroll
                for (int kc = 0; kc < 4; kc++) {
                    LDM4(bh[kc], sWHa + bo + kc * 32);
                    LDM4(bl[kc], sWLa + bo + kc * 32);
                }

                // 4 chains of 6 MMAs: acc[nh][half], half = kc{0,1} vs kc{2,3}
                float acc[2][2][4] = {{{0,0,0,0},{0,0,0,0}},{{0,0,0,0},{0,0,0,0}}};
                #pragma unroll
                for (int kc = 0; kc < 2; kc++)
                    #pragma unroll
                    for (int nh = 0; nh < 2; nh++) {
                        MMA(acc[nh][0], ah[kc],   bh[kc][2*nh],   bh[kc][2*nh+1]);
                        MMA(acc[nh][1], ah[kc+2], bh[kc+2][2*nh], bh[kc+2][2*nh+1]);
                    }
                #pragma unroll
                for (int kc = 0; kc < 2; kc++)
                    #pragma unroll
                    for (int nh = 0; nh < 2; nh++) {
                        MMA(acc[nh][0], al[kc],   bh[kc][2*nh],   bh[kc][2*nh+1]);
                        MMA(acc[nh][1], al[kc+2], bh[kc+2][2*nh], bh[kc+2][2*nh+1]);
                    }
                #pragma unroll
                for (int kc = 0; kc < 2; kc++)
                    #pragma unroll
                    for (int nh = 0; nh < 2; nh++) {
                        MMA(acc[nh][0], ah[kc],   bl[kc][2*nh],   bl[kc][2*nh+1]);
                        MMA(acc[nh][1], ah[kc+2], bl[kc+2][2*nh], bl[kc+2][2*nh+1]);
                    }

                const int n0 = nb + 2 * q;
                float2 tv0 = *(const float2*)(sT + n0);
                float2 tv1 = *(const float2*)(sT + n0 + 8);
                #pragma unroll
                for (int sl = 0; sl < 2; sl++) {
                    float v0 = (acc[0][0][sl*2]   + tv0.x) + acc[0][1][sl*2];
                    float v1 = (acc[0][0][sl*2+1] + tv0.y) + acc[0][1][sl*2+1];
                    float v2 = (acc[1][0][sl*2]   + tv1.x) + acc[1][1][sl*2];
                    float v3 = (acc[1][0][sl*2+1] + tv1.y) + acc[1][1][sl*2+1];
                    if (v0 > mx[sl]) { mx[sl] = v0; ix[sl] = n0; }
                    if (v1 > mx[sl]) { mx[sl] = v1; ix[sl] = n0 + 1; }
                    if (v2 > mx[sl]) { mx[sl] = v2; ix[sl] = n0 + 8; }
                    if (v3 > mx[sl]) { mx[sl] = v3; ix[sl] = n0 + 9; }
                }
            }

            #pragma unroll
            for (int sl = 0; sl < 2; sl++) {
                #pragma unroll
                for (int off = 1; off <= 2; off <<= 1) {
                    float ov = __shfl_xor_sync(0xFFFFFFFFu, mx[sl], off);
                    int   oi = __shfl_xor_sync(0xFFFFFFFFu, ix[sl], off);
                    if (ov > mx[sl] || (ov == mx[sl] && oi < ix[sl])) { mx[sl] = ov; ix[sl] = oi; }
                }
                if (mx[sl] < mn[sl]) { mn[sl] = mx[sl]; mi[sl] = ix[sl]; }
            }
        };

        #pragma unroll 1
        for (int g = 0; g < 4; g++) do_group(g);

        // prefetch tile i+2 into regs (latency hidden by groups 4-7)
        if (hasNext2) {
            const int rb = (tile + 2 * GRID) * TILE;
            #pragma unroll
            for (int k = 0; k < 8; k++) {
                int i = tid + k * THREADS;
                int gr = rb + (i >> 4); if (gr >= n) gr = n - 1;
                float4 v = ((const float4*)(x + (size_t)gr * NFEAT))[i & 15];
                split_pack(v.x, v.y, hw[k][0], lw[k][0]);
                split_pack(v.z, v.w, hw[k][1], lw[k][1]);
            }
        }

        #pragma unroll 1
        for (int g = 4; g < 8; g++) do_group(g);

        if (q == 0) {
            #pragma unroll
            for (int sl = 0; sl < 2; sl++) {
                int row = rbase + wid * 16 + (lane >> 2) + sl * 8;
                if (row < n) {
                    y[row] = mn[sl];
                    atomicAdd(&sH[mi[sl]], 1);
                }
            }
        }
        __syncthreads();    // STS visible + hist done before next tile
    }

    for (int i = tid; i < KH; i += THREADS) {
        int c = sH[i];
        if (c) atomicAdd(&A[i], (float)c);
    }
}

extern "C" void kernel_launch(void* const* d_in, const int* in_sizes, int n_in,
                              void* d_out, int out_size)
{
    const float* x = (const float*)d_in[0];   // [N, 64]
    const float* z = (const float*)d_in[1];   // [8, 64, 64]
    const float* t = (const float*)d_in[2];   // [8, 64]
    const int n = in_sizes[0] / NFEAT;
    const int ntiles = (n + TILE - 1) / TILE;

    float* y = (float*)d_out;
    float* A = (float*)d_out + n;

    cudaFuncSetAttribute(mnn_mma, cudaFuncAttributeMaxDynamicSharedMemorySize, SM_TOTAL);

    prep_k<<<(KH * NFEAT + 255) / 256, 256>>>(z);
    zero_k<<<1, KH>>>(A);
    dummy_k<<<1, 32>>>();                       // positions main at flat launch #4 for ncu
    mnn_mma<<<GRID, THREADS, SM_TOTAL>>>(x, t, y, A, n, ntiles);
}